// round 6
// baseline (speedup 1.0000x reference)
#include <cuda_runtime.h>
#include <cstdint>

#define Bk   64
#define Sk   4096
#define EMBk 20
#define HIDk 20
#define VOC  256

// Scratch (static device allocations are allowed; runtime allocs are not)
__device__ float g_xproj[Bk * Sk * 80];   // x@W_ih.T + b (sigmoid rows pre-halved)
__device__ float g_dist[Bk * 40];         // sum over S of emb (for dist_vector)
__device__ float g_h[Bk * 20];            // final LSTM hidden state

typedef unsigned long long u64;

__device__ __forceinline__ float fsig(float x) {
    return __fdividef(1.f, 1.f + __expf(-x));
}

// HW tanh (MUFU.TANH): lat ~16 vs ~44 for exp/div chain
__device__ __forceinline__ float ftanh_hw(float x) {
    float y; asm("tanh.approx.f32 %0, %1;" : "=f"(y) : "f"(x)); return y;
}

// packed f32x2 helpers (Blackwell packed fp32 pipe — PTX-only encodings)
__device__ __forceinline__ u64 pk2(float lo, float hi) {
    u64 r; asm("mov.b64 %0, {%1, %2};" : "=l"(r) : "f"(lo), "f"(hi)); return r;
}
__device__ __forceinline__ u64 ffma2(u64 a, u64 b, u64 c) {
    u64 d; asm("fma.rn.f32x2 %0, %1, %2, %3;" : "=l"(d) : "l"(a), "l"(b), "l"(c));
    return d;
}
__device__ __forceinline__ u64 fadd2(u64 a, u64 b) {
    u64 d; asm("add.rn.f32x2 %0, %1, %2;" : "=l"(d) : "l"(a), "l"(b));
    return d;
}
__device__ __forceinline__ float hadd2(u64 v) {
    float lo, hi; asm("mov.b64 {%0, %1}, %2;" : "=f"(lo), "=f"(hi) : "l"(v));
    return lo + hi;
}

// ---------------------------------------------------------------------------
// init: zero the dist accumulator (must be deterministic per launch)
// ---------------------------------------------------------------------------
__global__ void initk() {
    int i = blockIdx.x * blockDim.x + threadIdx.x;
    if (i < Bk * 40) g_dist[i] = 0.f;
}

// ---------------------------------------------------------------------------
// Phase 1: byte-embedding gather + encoder (sigmoid MLP) + x-projection.
// Sigmoid-gate rows (j<40 or j>=60) of the projection are PRE-SCALED by 0.5
// (tanh-identity form used by phase2). grid (16,64).
// ---------------------------------------------------------------------------
__global__ void __launch_bounds__(256) phase1(
    const int* __restrict__ inp,
    const float* __restrict__ pc_emb, const float* __restrict__ addr_emb,
    const float* __restrict__ enc_W, const float* __restrict__ enc_b,
    const float* __restrict__ W_ih, const float* __restrict__ b_ih,
    const float* __restrict__ b_hh)
{
    __shared__ float sWe[20 * 80];
    __shared__ float sWih[80 * 40];
    __shared__ float sbe[20];
    __shared__ float sbs[80];
    __shared__ float ssum[40];

    int tid = threadIdx.x;
    for (int i = tid; i < 1600; i += 256) sWe[i] = enc_W[i];
    for (int i = tid; i < 3200; i += 256) {
        int row = i / 40;
        float sc = (row >= 40 && row < 60) ? 1.f : 0.5f;
        sWih[i] = W_ih[i] * sc;
    }
    if (tid < 20) sbe[tid] = enc_b[tid];
    if (tid < 80) {
        float sc = (tid >= 40 && tid < 60) ? 1.f : 0.5f;
        sbs[tid] = (b_ih[tid] + b_hh[tid]) * sc;
    }
    if (tid < 40) ssum[tid] = 0.f;
    __syncthreads();

    int b = blockIdx.y;
    int s = blockIdx.x * 256 + tid;
    int2 pv = ((const int2*)inp)[b * Sk + s];

    float emb[40];

    #pragma unroll
    for (int p = 0; p < 2; p++) {
        unsigned val = (unsigned)(p ? pv.y : pv.x);
        const float* tab = p ? addr_emb : pc_emb;
        float acc[20];
        #pragma unroll
        for (int o = 0; o < 20; o++) acc[o] = sbe[o];

        #pragma unroll 1
        for (int i = 0; i < 4; i++) {
            unsigned byt = (val >> (24 - 8 * i)) & 0xFFu;
            const float4* row = (const float4*)(tab + (i * 256 + (int)byt) * 20);
            float4 g0 = __ldg(row), g1 = __ldg(row + 1), g2 = __ldg(row + 2),
                   g3 = __ldg(row + 3), g4 = __ldg(row + 4);
            const float4* wb = ((const float4*)sWe) + i * 5;
            #pragma unroll
            for (int o = 0; o < 20; o++) {
                const float4* wo = wb + o * 20;
                float4 w0 = wo[0], w1 = wo[1], w2 = wo[2], w3 = wo[3], w4 = wo[4];
                float a = acc[o];
                a += g0.x * w0.x + g0.y * w0.y + g0.z * w0.z + g0.w * w0.w;
                a += g1.x * w1.x + g1.y * w1.y + g1.z * w1.z + g1.w * w1.w;
                a += g2.x * w2.x + g2.y * w2.y + g2.z * w2.z + g2.w * w2.w;
                a += g3.x * w3.x + g3.y * w3.y + g3.z * w3.z + g3.w * w3.w;
                a += g4.x * w4.x + g4.y * w4.y + g4.z * w4.z + g4.w * w4.w;
                acc[o] = a;
            }
        }
        #pragma unroll
        for (int o = 0; o < 20; o++) emb[p * 20 + o] = fsig(acc[o]);
    }

    // x-projection: 80 outputs, K = 40. 4 outputs per rolled iteration.
    {
        float4* outp = (float4*)g_xproj + (b * Sk + s) * 20;
        const float4* wih4 = (const float4*)sWih;
        #pragma unroll 1
        for (int jq = 0; jq < 20; jq++) {
            float a0 = sbs[jq * 4 + 0], a1 = sbs[jq * 4 + 1];
            float a2 = sbs[jq * 4 + 2], a3 = sbs[jq * 4 + 3];
            #pragma unroll
            for (int e4 = 0; e4 < 10; e4++) {
                float x0 = emb[e4 * 4 + 0], x1 = emb[e4 * 4 + 1];
                float x2 = emb[e4 * 4 + 2], x3 = emb[e4 * 4 + 3];
                float4 w;
                w = wih4[(jq * 4 + 0) * 10 + e4];
                a0 += w.x * x0 + w.y * x1 + w.z * x2 + w.w * x3;
                w = wih4[(jq * 4 + 1) * 10 + e4];
                a1 += w.x * x0 + w.y * x1 + w.z * x2 + w.w * x3;
                w = wih4[(jq * 4 + 2) * 10 + e4];
                a2 += w.x * x0 + w.y * x1 + w.z * x2 + w.w * x3;
                w = wih4[(jq * 4 + 3) * 10 + e4];
                a3 += w.x * x0 + w.y * x1 + w.z * x2 + w.w * x3;
            }
            outp[jq] = make_float4(a0, a1, a2, a3);
        }
    }

    // dist_vector accumulation
    #pragma unroll
    for (int e = 0; e < 40; e++) {
        float v2 = emb[e];
        v2 += __shfl_xor_sync(0xffffffffu, v2, 16);
        v2 += __shfl_xor_sync(0xffffffffu, v2, 8);
        v2 += __shfl_xor_sync(0xffffffffu, v2, 4);
        v2 += __shfl_xor_sync(0xffffffffu, v2, 2);
        v2 += __shfl_xor_sync(0xffffffffu, v2, 1);
        if ((tid & 31) == 0) atomicAdd(&ssum[e], v2);
    }
    __syncthreads();
    if (tid < 40) atomicAdd(&g_dist[b * 40 + tid], ssum[tid]);
}

// ---------------------------------------------------------------------------
// Phase 2: sequential LSTM, ONE WARP per batch element.
// Slot mapping (3 dot slots cover all 80 gates):
//   slot0: lanes 0-19 -> i_l      lanes 20-31 -> o_{l-20} (rows 60-71)
//   slot1: lanes 0-19 -> f_l      lanes 20-27 -> o_{l-8}  (rows 72-79)
//   slot2: lanes 0-19 -> g_l      lanes 20-31 -> dummy (row 79)
// h exchange via smem: lanes 0-19 STS hn -> bar.sync (3 cyc @ 1 warp) -> all
// lanes 5x LDS.128 (packed f32x2 pairs, no movs) — replaces 20 SHFL + 10 pk2.
// h reload sits at the END of the step (LDS latency hides in the back-edge);
// x loads are software-pipelined one step ahead. MUFU.TANH activations;
// sigmoid 0.5 pre-folded into W_hh rows AND g_xproj rows (phase1).
// ---------------------------------------------------------------------------
__global__ void __launch_bounds__(32) phase2(
    const float* __restrict__ h0, const float* __restrict__ c0,
    const float* __restrict__ W_hh)
{
    __shared__ __align__(16) float xs[2][32 * 80];
    __shared__ __align__(16) float hsm[20];
    const int lane = threadIdx.x;
    const int b = blockIdx.x;

    const int r0 = (lane < 20) ? lane      : 40 + lane;               // 60..71
    const int r1 = (lane < 20) ? 20 + lane : (lane < 28 ? 52 + lane : 79);
    const int r2 = (lane < 20) ? 40 + lane : 79;

    // slot0/slot1 rows are ALL sigmoid rows -> pre-scale by 0.5 (tanh identity)
    u64 w0[10], w1[10], w2s[10];
    #pragma unroll
    for (int k = 0; k < 10; k++) {
        float2 a;
        a = ((const float2*)(W_hh + r0 * 20))[k]; w0[k]  = pk2(0.5f * a.x, 0.5f * a.y);
        a = ((const float2*)(W_hh + r1 * 20))[k]; w1[k]  = pk2(0.5f * a.x, 0.5f * a.y);
        a = ((const float2*)(W_hh + r2 * 20))[k]; w2s[k] = pk2(a.x, a.y);
    }
    float c = (lane < 20) ? c0[b * 20 + lane] : 0.f;
    if (lane < 20) hsm[lane] = h0[b * 20 + lane];

    const float4* src = (const float4*)g_xproj + (size_t)b * (Sk * 20);
    unsigned sm0 = (unsigned)__cvta_generic_to_shared(&xs[0][0]);

    auto refill = [&](int chunk, int buf) {
        unsigned d = sm0 + (unsigned)buf * (2560u * 4u);
        const float4* s = src + chunk * 640;
        #pragma unroll
        for (int q = 0; q < 20; q++) {
            unsigned da = d + (unsigned)(lane + 32 * q) * 16u;
            const float4* sa = s + lane + 32 * q;
            asm volatile("cp.async.cg.shared.global [%0], [%1], 16;"
                         :: "r"(da), "l"(sa));
        }
        asm volatile("cp.async.commit_group;");
    };

    refill(0, 0);
    refill(1, 1);
    asm volatile("cp.async.wait_group 1;");
    __syncthreads();   // buffer 0 visible + h0 in hsm

    // initial packed h
    u64 hh[10];
    #pragma unroll
    for (int k = 0; k < 5; k++) {
        ulonglong2 p = ((const ulonglong2*)hsm)[k];
        hh[2 * k] = p.x; hh[2 * k + 1] = p.y;
    }

    float hn = 0.f;
    const u64 Z2 = pk2(0.f, 0.f);
    const int NC = Sk / 32;
    for (int ci = 0; ci < NC; ci++) {
        const float* xb = &xs[ci & 1][0];
        // x for t=0 of this chunk (buffer just became visible)
        float x0 = xb[r0], x1 = xb[r1], x2 = xb[r2];
        #pragma unroll 1
        for (int t = 0; t < 32; t++) {
            u64 aA = pk2(x0, 0.f), aB = Z2;
            u64 bA = pk2(x1, 0.f), bB = Z2;
            u64 cA = pk2(x2, 0.f), cB = Z2;
            // prefetch next step's x (independent; hides under the math)
            float nx0 = 0.f, nx1 = 0.f, nx2 = 0.f;
            if (t < 31) {
                const float* xn = xb + (t + 1) * 80;
                nx0 = xn[r0]; nx1 = xn[r1]; nx2 = xn[r2];
            }
            // 2-way tree per slot over packed h pairs
            #pragma unroll
            for (int k = 0; k < 5; k++) {
                aA = ffma2(w0[k],      hh[k],     aA);
                bA = ffma2(w1[k],      hh[k],     bA);
                cA = ffma2(w2s[k],     hh[k],     cA);
                aB = ffma2(w0[k + 5],  hh[k + 5], aB);
                bB = ffma2(w1[k + 5],  hh[k + 5], bB);
                cB = ffma2(w2s[k + 5], hh[k + 5], cB);
            }
            float s0 = __fmaf_rn(0.5f, ftanh_hw(hadd2(fadd2(aA, aB))), 0.5f);
            float s1 = __fmaf_rn(0.5f, ftanh_hw(hadd2(fadd2(bA, bB))), 0.5f);
            float tg = ftanh_hw(hadd2(fadd2(cA, cB)));

            float oA = __shfl_sync(0xffffffffu, s0, lane + 20);
            float oB = __shfl_sync(0xffffffffu, s1, lane + 8);
            float o  = (lane < 12) ? oA : oB;

            c  = __fmaf_rn(s1, c, s0 * tg);      // f*c + i*g
            hn = o * ftanh_hw(c);                // o * tanh(c)

            if (lane < 20) hsm[lane] = hn;
            __syncthreads();                     // 1 warp -> BAR floor ~3 cyc
            #pragma unroll
            for (int k = 0; k < 5; k++) {
                ulonglong2 p = ((const ulonglong2*)hsm)[k];
                hh[2 * k] = p.x; hh[2 * k + 1] = p.y;
            }
            x0 = nx0; x1 = nx1; x2 = nx2;
        }
        if (ci + 1 < NC) {
            asm volatile("cp.async.wait_group 0;");
            __syncthreads();
            if (ci + 2 < NC) refill(ci + 2, ci & 1);
        }
    }
    if (lane < 20) g_h[b * 20 + lane] = hn;
}

// ---------------------------------------------------------------------------
// Phase 3a: logits + batch-axis softmax. One warp per (k, v); lane handles
// batches (lane, lane+32). Writes probs at out[0..], logits at out[65536..].
// ---------------------------------------------------------------------------
__global__ void __launch_bounds__(256) phase3a(
    const float* __restrict__ dec_W, const float* __restrict__ dec_b,
    float* __restrict__ out)
{
    __shared__ float hs[64 * 20];
    for (int i = threadIdx.x; i < 1280; i += 256) hs[i] = g_h[i];
    __syncthreads();

    int warp = blockIdx.x * 8 + (threadIdx.x >> 5);
    int lane = threadIdx.x & 31;
    int k = warp >> 8, v = warp & 255;

    const float* wrow = dec_W + (k * 256 + v) * 20;
    float w[20];
    #pragma unroll
    for (int e = 0; e < 20; e++) w[e] = __ldg(wrow + e);
    float bb = __ldg(dec_b + k * 256 + v);

    int b0 = lane, b1 = lane + 32;
    float l0 = bb, l1 = bb;
    #pragma unroll
    for (int e = 0; e < 20; e++) {
        l0 += hs[b0 * 20 + e] * w[e];
        l1 += hs[b1 * 20 + e] * w[e];
    }
    out[65536 + (k * 64 + b0) * 256 + v] = l0;
    out[65536 + (k * 64 + b1) * 256 + v] = l1;

    float s0 = l0 / 0.001f, s1 = l1 / 0.001f;   // exact div, mirrors reference
    float m = fmaxf(s0, s1);
    #pragma unroll
    for (int o = 16; o > 0; o >>= 1) m = fmaxf(m, __shfl_xor_sync(0xffffffffu, m, o));
    float p0 = __expf(s0 - m), p1 = __expf(s1 - m);
    float sum = p0 + p1;
    #pragma unroll
    for (int o = 16; o > 0; o >>= 1) sum += __shfl_xor_sync(0xffffffffu, sum, o);
    float inv = __fdividef(1.f, sum);
    out[(k * 64 + b0) * 256 + v] = p0 * inv;
    out[(k * 64 + b1) * 256 + v] = p1 * inv;
}

// ---------------------------------------------------------------------------
// Phase 3b: byte_e = probs @ addr_emb, fe = encoder(byte_e), freq_rec head.
// One CTA per batch element.
// ---------------------------------------------------------------------------
__global__ void __launch_bounds__(128) phase3b(
    const float* __restrict__ addr_emb,
    const float* __restrict__ enc_W, const float* __restrict__ enc_b,
    const float* __restrict__ d1_W, const float* __restrict__ d1_b,
    const float* __restrict__ d2_W, const float* __restrict__ d2_b,
    float* __restrict__ out)
{
    __shared__ float ps[4 * 256];
    __shared__ float xv[80];
    __shared__ float fr_in[60];
    __shared__ float r1[10];

    int b = blockIdx.x, tid = threadIdx.x;
    for (int i = tid; i < 1024; i += 128) {
        int k = i >> 8, v = i & 255;
        ps[i] = out[(k * 64 + b) * 256 + v];
    }
    __syncthreads();

    if (tid < 80) {
        int k = tid / 20, e = tid % 20;
        float acc = 0.f;
        const float* ae = addr_emb + k * 256 * 20 + e;
        const float* pk = ps + k * 256;
        #pragma unroll 8
        for (int v = 0; v < 256; v++) acc += pk[v] * __ldg(ae + v * 20);
        xv[tid] = acc;
    }
    __syncthreads();

    if (tid < 20) {
        float a = enc_b[tid];
        #pragma unroll 8
        for (int e = 0; e < 80; e++) a += xv[e] * enc_W[tid * 80 + e];
        fr_in[tid] = fsig(a);
    }
    if (tid >= 64 && tid < 104) {
        int e = tid - 64;
        fr_in[20 + e] = g_dist[b * 40 + e] * (1.0f / 4096.0f);
    }
    __syncthreads();

    if (tid < 10) {
        float a = d1_b[tid];
        #pragma unroll
        for (int e = 0; e < 60; e++) a += fr_in[e] * d1_W[tid * 60 + e];
        r1[tid] = fmaxf(a, 0.f);
    }
    __syncthreads();

    if (tid < 2) {
        float a = d2_b[tid];
        #pragma unroll
        for (int e = 0; e < 10; e++) a += r1[e] * d2_W[tid * 10 + e];
        out[131072 + tid * 64 + b] = a;
    }
}

// ---------------------------------------------------------------------------
extern "C" void kernel_launch(void* const* d_in, const int* in_sizes, int n_in,
                              void* d_out, int out_size)
{
    const int*   inp      = (const int*)d_in[0];
    const float* h0       = (const float*)d_in[1];
    const float* c0       = (const float*)d_in[2];
    const float* pc_emb   = (const float*)d_in[3];
    const float* addr_emb = (const float*)d_in[4];
    const float* enc_W    = (const float*)d_in[5];
    const float* enc_b    = (const float*)d_in[6];
    const float* W_ih     = (const float*)d_in[7];
    const float* W_hh     = (const float*)d_in[8];
    const float* b_ih     = (const float*)d_in[9];
    const float* b_hh     = (const float*)d_in[10];
    const float* dec_W    = (const float*)d_in[11];
    const float* dec_b    = (const float*)d_in[12];
    const float* d1_W     = (const float*)d_in[13];
    const float* d1_b     = (const float*)d_in[14];
    const float* d2_W     = (const float*)d_in[15];
    const float* d2_b     = (const float*)d_in[16];
    float* out = (float*)d_out;

    initk<<<10, 256>>>();
    phase1<<<dim3(16, 64), 256>>>(inp, pc_emb, addr_emb, enc_W, enc_b,
                                  W_ih, b_ih, b_hh);
    phase2<<<64, 32>>>(h0, c0, W_hh);
    phase3a<<<128, 256>>>(dec_W, dec_b, out);
    phase3b<<<64, 128>>>(addr_emb, enc_W, enc_b, d1_W, d1_b, d2_W, d2_b, out);
}

// round 7
// speedup vs baseline: 1.0513x; 1.0513x over previous
#include <cuda_runtime.h>
#include <cstdint>

#define Bk   64
#define Sk   4096
#define EMBk 20
#define HIDk 20
#define VOC  256

// Scratch (static device allocations are allowed; runtime allocs are not)
__device__ float g_xproj[Bk * Sk * 80];   // x@W_ih.T + b (sigmoid rows pre-halved)
__device__ float g_dist[Bk * 40];         // sum over S of emb (for dist_vector)
__device__ float g_h[Bk * 20];            // final LSTM hidden state

typedef unsigned long long u64;

__device__ __forceinline__ float fsig(float x) {
    return __fdividef(1.f, 1.f + __expf(-x));
}

// HW tanh (MUFU.TANH): lat ~16 vs ~44 for exp/div chain
__device__ __forceinline__ float ftanh_hw(float x) {
    float y; asm("tanh.approx.f32 %0, %1;" : "=f"(y) : "f"(x)); return y;
}

// packed f32x2 helpers (Blackwell packed fp32 pipe — PTX-only encodings)
__device__ __forceinline__ u64 pk2(float lo, float hi) {
    u64 r; asm("mov.b64 %0, {%1, %2};" : "=l"(r) : "f"(lo), "f"(hi)); return r;
}
__device__ __forceinline__ u64 ffma2(u64 a, u64 b, u64 c) {
    u64 d; asm("fma.rn.f32x2 %0, %1, %2, %3;" : "=l"(d) : "l"(a), "l"(b), "l"(c));
    return d;
}
__device__ __forceinline__ u64 fadd2(u64 a, u64 b) {
    u64 d; asm("add.rn.f32x2 %0, %1, %2;" : "=l"(d) : "l"(a), "l"(b));
    return d;
}
__device__ __forceinline__ float hadd2(u64 v) {
    float lo, hi; asm("mov.b64 {%0, %1}, %2;" : "=f"(lo), "=f"(hi) : "l"(v));
    return lo + hi;
}

// ---------------------------------------------------------------------------
// init: zero the dist accumulator (must be deterministic per launch)
// ---------------------------------------------------------------------------
__global__ void initk() {
    int i = blockIdx.x * blockDim.x + threadIdx.x;
    if (i < Bk * 40) g_dist[i] = 0.f;
}

// ---------------------------------------------------------------------------
// Phase 1: byte-embedding gather + encoder (sigmoid MLP) + x-projection.
// ALL dot products in packed fma.f32x2 over the K dimension (rows are
// K-contiguous -> pairs are direct 64-bit loads, no repacking).
// Sigmoid-gate rows (j<40 or j>=60) of the projection are PRE-SCALED by 0.5
// (tanh-identity form used by phase2). grid (16,64).
// ---------------------------------------------------------------------------
__global__ void __launch_bounds__(256) phase1(
    const int* __restrict__ inp,
    const float* __restrict__ pc_emb, const float* __restrict__ addr_emb,
    const float* __restrict__ enc_W, const float* __restrict__ enc_b,
    const float* __restrict__ W_ih, const float* __restrict__ b_ih,
    const float* __restrict__ b_hh)
{
    __shared__ __align__(16) float sWe[20 * 80];
    __shared__ __align__(16) float sWih[80 * 40];
    __shared__ float sbe[20];
    __shared__ float sbs[80];
    __shared__ float ssum[40];

    int tid = threadIdx.x;
    for (int i = tid; i < 1600; i += 256) sWe[i] = enc_W[i];
    for (int i = tid; i < 3200; i += 256) {
        int row = i / 40;
        float sc = (row >= 40 && row < 60) ? 1.f : 0.5f;
        sWih[i] = W_ih[i] * sc;
    }
    if (tid < 20) sbe[tid] = enc_b[tid];
    if (tid < 80) {
        float sc = (tid >= 40 && tid < 60) ? 1.f : 0.5f;
        sbs[tid] = (b_ih[tid] + b_hh[tid]) * sc;
    }
    if (tid < 40) ssum[tid] = 0.f;
    __syncthreads();

    int b = blockIdx.y;
    int s = blockIdx.x * 256 + tid;
    int2 pv = ((const int2*)inp)[b * Sk + s];

    float emb[40];

    #pragma unroll
    for (int p = 0; p < 2; p++) {
        unsigned val = (unsigned)(p ? pv.y : pv.x);
        const float* tab = p ? addr_emb : pc_emb;
        u64 acc2[20];
        #pragma unroll
        for (int o = 0; o < 20; o++) acc2[o] = pk2(sbe[o], 0.f);

        #pragma unroll 1
        for (int i = 0; i < 4; i++) {
            unsigned byt = (val >> (24 - 8 * i)) & 0xFFu;
            const ulonglong2* row =
                (const ulonglong2*)(tab + (i * 256 + (int)byt) * 20);
            ulonglong2 G0 = __ldg(row),     G1 = __ldg(row + 1),
                       G2 = __ldg(row + 2), G3 = __ldg(row + 3),
                       G4 = __ldg(row + 4);
            #pragma unroll
            for (int o = 0; o < 20; o++) {
                const ulonglong2* wo = (const ulonglong2*)(sWe + o * 80 + i * 20);
                ulonglong2 w0 = wo[0], w1 = wo[1], w2 = wo[2], w3 = wo[3],
                           w4 = wo[4];
                u64 a = acc2[o];
                a = ffma2(w0.x, G0.x, a); a = ffma2(w0.y, G0.y, a);
                a = ffma2(w1.x, G1.x, a); a = ffma2(w1.y, G1.y, a);
                a = ffma2(w2.x, G2.x, a); a = ffma2(w2.y, G2.y, a);
                a = ffma2(w3.x, G3.x, a); a = ffma2(w3.y, G3.y, a);
                a = ffma2(w4.x, G4.x, a); a = ffma2(w4.y, G4.y, a);
                acc2[o] = a;
            }
        }
        #pragma unroll
        for (int o = 0; o < 20; o++) emb[p * 20 + o] = fsig(hadd2(acc2[o]));
    }

    // x-projection: 80 outputs, K = 40 packed as 20 f32x2 pairs.
    {
        u64 x2[20];
        #pragma unroll
        for (int m = 0; m < 20; m++) x2[m] = pk2(emb[2 * m], emb[2 * m + 1]);

        float4* outp = (float4*)g_xproj + (b * Sk + s) * 20;
        #pragma unroll 1
        for (int jq = 0; jq < 20; jq++) {
            u64 A0 = pk2(sbs[jq * 4 + 0], 0.f);
            u64 A1 = pk2(sbs[jq * 4 + 1], 0.f);
            u64 A2 = pk2(sbs[jq * 4 + 2], 0.f);
            u64 A3 = pk2(sbs[jq * 4 + 3], 0.f);
            const u64* w0 = (const u64*)(sWih + (jq * 4 + 0) * 40);
            const u64* w1 = (const u64*)(sWih + (jq * 4 + 1) * 40);
            const u64* w2 = (const u64*)(sWih + (jq * 4 + 2) * 40);
            const u64* w3 = (const u64*)(sWih + (jq * 4 + 3) * 40);
            #pragma unroll
            for (int m = 0; m < 20; m++) {
                u64 xm = x2[m];
                A0 = ffma2(w0[m], xm, A0);
                A1 = ffma2(w1[m], xm, A1);
                A2 = ffma2(w2[m], xm, A2);
                A3 = ffma2(w3[m], xm, A3);
            }
            outp[jq] = make_float4(hadd2(A0), hadd2(A1), hadd2(A2), hadd2(A3));
        }
    }

    // dist_vector accumulation
    #pragma unroll
    for (int e = 0; e < 40; e++) {
        float v2 = emb[e];
        v2 += __shfl_xor_sync(0xffffffffu, v2, 16);
        v2 += __shfl_xor_sync(0xffffffffu, v2, 8);
        v2 += __shfl_xor_sync(0xffffffffu, v2, 4);
        v2 += __shfl_xor_sync(0xffffffffu, v2, 2);
        v2 += __shfl_xor_sync(0xffffffffu, v2, 1);
        if ((tid & 31) == 0) atomicAdd(&ssum[e], v2);
    }
    __syncthreads();
    if (tid < 40) atomicAdd(&g_dist[b * 40 + tid], ssum[tid]);
}

// ---------------------------------------------------------------------------
// Phase 2: sequential LSTM, ONE WARP per batch element (round-5 structure —
// the best measured variant). Slot mapping (3 dot slots cover all 80 gates):
//   slot0: lanes 0-19 -> i_l      lanes 20-31 -> o_{l-20} (rows 60-71)
//   slot1: lanes 0-19 -> f_l      lanes 20-27 -> o_{l-8}  (rows 72-79)
//   slot2: lanes 0-19 -> g_l      lanes 20-31 -> dummy (row 79)
// Inline h-broadcast via SHFL overlapping the 2-way-tree fma.f32x2 chains.
// Sigmoid 0.5 now pre-folded into g_xproj (phase1), so x is used directly.
// t-loop unrolled x2 so ptxas can pipeline x-loads across steps.
// ---------------------------------------------------------------------------
__global__ void __launch_bounds__(32) phase2(
    const float* __restrict__ h0, const float* __restrict__ c0,
    const float* __restrict__ W_hh)
{
    __shared__ __align__(16) float xs[2][32 * 80];
    const int lane = threadIdx.x;
    const int b = blockIdx.x;

    const int r0 = (lane < 20) ? lane      : 40 + lane;               // 60..71
    const int r1 = (lane < 20) ? 20 + lane : (lane < 28 ? 52 + lane : 79);
    const int r2 = (lane < 20) ? 40 + lane : 79;

    // slot0/slot1 rows are ALL sigmoid rows -> pre-scale by 0.5 (tanh identity)
    u64 w0[10], w1[10], w2s[10];
    #pragma unroll
    for (int k = 0; k < 10; k++) {
        float2 a;
        a = ((const float2*)(W_hh + r0 * 20))[k]; w0[k]  = pk2(0.5f * a.x, 0.5f * a.y);
        a = ((const float2*)(W_hh + r1 * 20))[k]; w1[k]  = pk2(0.5f * a.x, 0.5f * a.y);
        a = ((const float2*)(W_hh + r2 * 20))[k]; w2s[k] = pk2(a.x, a.y);
    }
    float hn = (lane < 20) ? h0[b * 20 + lane] : 0.f;
    float c  = (lane < 20) ? c0[b * 20 + lane] : 0.f;

    const float4* src = (const float4*)g_xproj + (size_t)b * (Sk * 20);
    unsigned sm0 = (unsigned)__cvta_generic_to_shared(&xs[0][0]);

    auto refill = [&](int chunk, int buf) {
        unsigned d = sm0 + (unsigned)buf * (2560u * 4u);
        const float4* s = src + chunk * 640;
        #pragma unroll
        for (int q = 0; q < 20; q++) {
            unsigned da = d + (unsigned)(lane + 32 * q) * 16u;
            const float4* sa = s + lane + 32 * q;
            asm volatile("cp.async.cg.shared.global [%0], [%1], 16;"
                         :: "r"(da), "l"(sa));
        }
        asm volatile("cp.async.commit_group;");
    };

    refill(0, 0);
    refill(1, 1);
    asm volatile("cp.async.wait_group 1;");
    __syncwarp();

    const u64 Z2 = pk2(0.f, 0.f);
    const int NC = Sk / 32;
    for (int ci = 0; ci < NC; ci++) {
        const float* xb = &xs[ci & 1][0];
        #pragma unroll 2
        for (int t = 0; t < 32; t++) {
            const float* xt = xb + t * 80;
            // hoist x loads: LDS latency hides under the shfl stream
            float x0 = xt[r0], x1 = xt[r1], x2 = xt[r2];
            u64 aA = pk2(x0, 0.f), aB = Z2;
            u64 bA = pk2(x1, 0.f), bB = Z2;
            u64 cA = pk2(x2, 0.f), cB = Z2;
            // inline h-broadcast: shfl latency overlaps the fma.f32x2 chains.
            // 2-way tree per slot: k=0..4 -> *A, k=5..9 -> *B (independent).
            #pragma unroll
            for (int k = 0; k < 5; k++) {
                float lo0 = __shfl_sync(0xffffffffu, hn, 2 * k);
                float hi0 = __shfl_sync(0xffffffffu, hn, 2 * k + 1);
                u64 hh0 = pk2(lo0, hi0);
                float lo1 = __shfl_sync(0xffffffffu, hn, 2 * k + 10);
                float hi1 = __shfl_sync(0xffffffffu, hn, 2 * k + 11);
                u64 hh1 = pk2(lo1, hi1);
                aA = ffma2(w0[k],      hh0, aA);
                bA = ffma2(w1[k],      hh0, bA);
                cA = ffma2(w2s[k],     hh0, cA);
                aB = ffma2(w0[k + 5],  hh1, aB);
                bB = ffma2(w1[k + 5],  hh1, bB);
                cB = ffma2(w2s[k + 5], hh1, cB);
            }
            float s0 = __fmaf_rn(0.5f, ftanh_hw(hadd2(fadd2(aA, aB))), 0.5f);
            float s1 = __fmaf_rn(0.5f, ftanh_hw(hadd2(fadd2(bA, bB))), 0.5f);
            float tg = ftanh_hw(hadd2(fadd2(cA, cB)));

            float oA = __shfl_sync(0xffffffffu, s0, lane + 20);
            float oB = __shfl_sync(0xffffffffu, s1, lane + 8);
            float o  = (lane < 12) ? oA : oB;

            c  = __fmaf_rn(s1, c, s0 * tg);      // f*c + i*g
            hn = o * ftanh_hw(c);                // o * tanh(c)
        }
        if (ci + 1 < NC) {
            asm volatile("cp.async.wait_group 0;");
            __syncwarp();
            if (ci + 2 < NC) refill(ci + 2, ci & 1);
        }
    }
    if (lane < 20) g_h[b * 20 + lane] = hn;
}

// ---------------------------------------------------------------------------
// Phase 3a: logits + batch-axis softmax. One warp per (k, v); lane handles
// batches (lane, lane+32). Writes probs at out[0..], logits at out[65536..].
// ---------------------------------------------------------------------------
__global__ void __launch_bounds__(256) phase3a(
    const float* __restrict__ dec_W, const float* __restrict__ dec_b,
    float* __restrict__ out)
{
    __shared__ float hs[64 * 20];
    for (int i = threadIdx.x; i < 1280; i += 256) hs[i] = g_h[i];
    __syncthreads();

    int warp = blockIdx.x * 8 + (threadIdx.x >> 5);
    int lane = threadIdx.x & 31;
    int k = warp >> 8, v = warp & 255;

    const float* wrow = dec_W + (k * 256 + v) * 20;
    float w[20];
    #pragma unroll
    for (int e = 0; e < 20; e++) w[e] = __ldg(wrow + e);
    float bb = __ldg(dec_b + k * 256 + v);

    int b0 = lane, b1 = lane + 32;
    float l0 = bb, l1 = bb;
    #pragma unroll
    for (int e = 0; e < 20; e++) {
        l0 += hs[b0 * 20 + e] * w[e];
        l1 += hs[b1 * 20 + e] * w[e];
    }
    out[65536 + (k * 64 + b0) * 256 + v] = l0;
    out[65536 + (k * 64 + b1) * 256 + v] = l1;

    float s0 = l0 / 0.001f, s1 = l1 / 0.001f;   // exact div, mirrors reference
    float m = fmaxf(s0, s1);
    #pragma unroll
    for (int o = 16; o > 0; o >>= 1) m = fmaxf(m, __shfl_xor_sync(0xffffffffu, m, o));
    float p0 = __expf(s0 - m), p1 = __expf(s1 - m);
    float sum = p0 + p1;
    #pragma unroll
    for (int o = 16; o > 0; o >>= 1) sum += __shfl_xor_sync(0xffffffffu, sum, o);
    float inv = __fdividef(1.f, sum);
    out[(k * 64 + b0) * 256 + v] = p0 * inv;
    out[(k * 64 + b1) * 256 + v] = p1 * inv;
}

// ---------------------------------------------------------------------------
// Phase 3b: byte_e = probs @ addr_emb, fe = encoder(byte_e), freq_rec head.
// One CTA per batch element.
// ---------------------------------------------------------------------------
__global__ void __launch_bounds__(128) phase3b(
    const float* __restrict__ addr_emb,
    const float* __restrict__ enc_W, const float* __restrict__ enc_b,
    const float* __restrict__ d1_W, const float* __restrict__ d1_b,
    const float* __restrict__ d2_W, const float* __restrict__ d2_b,
    float* __restrict__ out)
{
    __shared__ float ps[4 * 256];
    __shared__ float xv[80];
    __shared__ float fr_in[60];
    __shared__ float r1[10];

    int b = blockIdx.x, tid = threadIdx.x;
    for (int i = tid; i < 1024; i += 128) {
        int k = i >> 8, v = i & 255;
        ps[i] = out[(k * 64 + b) * 256 + v];
    }
    __syncthreads();

    if (tid < 80) {
        int k = tid / 20, e = tid % 20;
        float acc = 0.f;
        const float* ae = addr_emb + k * 256 * 20 + e;
        const float* pk = ps + k * 256;
        #pragma unroll 8
        for (int v = 0; v < 256; v++) acc += pk[v] * __ldg(ae + v * 20);
        xv[tid] = acc;
    }
    __syncthreads();

    if (tid < 20) {
        float a = enc_b[tid];
        #pragma unroll 8
        for (int e = 0; e < 80; e++) a += xv[e] * enc_W[tid * 80 + e];
        fr_in[tid] = fsig(a);
    }
    if (tid >= 64 && tid < 104) {
        int e = tid - 64;
        fr_in[20 + e] = g_dist[b * 40 + e] * (1.0f / 4096.0f);
    }
    __syncthreads();

    if (tid < 10) {
        float a = d1_b[tid];
        #pragma unroll
        for (int e = 0; e < 60; e++) a += fr_in[e] * d1_W[tid * 60 + e];
        r1[tid] = fmaxf(a, 0.f);
    }
    __syncthreads();

    if (tid < 2) {
        float a = d2_b[tid];
        #pragma unroll
        for (int e = 0; e < 10; e++) a += r1[e] * d2_W[tid * 10 + e];
        out[131072 + tid * 64 + b] = a;
    }
}

// ---------------------------------------------------------------------------
extern "C" void kernel_launch(void* const* d_in, const int* in_sizes, int n_in,
                              void* d_out, int out_size)
{
    const int*   inp      = (const int*)d_in[0];
    const float* h0       = (const float*)d_in[1];
    const float* c0       = (const float*)d_in[2];
    const float* pc_emb   = (const float*)d_in[3];
    const float* addr_emb = (const float*)d_in[4];
    const float* enc_W    = (const float*)d_in[5];
    const float* enc_b    = (const float*)d_in[6];
    const float* W_ih     = (const float*)d_in[7];
    const float* W_hh     = (const float*)d_in[8];
    const float* b_ih     = (const float*)d_in[9];
    const float* b_hh     = (const float*)d_in[10];
    const float* dec_W    = (const float*)d_in[11];
    const float* dec_b    = (const float*)d_in[12];
    const float* d1_W     = (const float*)d_in[13];
    const float* d1_b     = (const float*)d_in[14];
    const float* d2_W     = (const float*)d_in[15];
    const float* d2_b     = (const float*)d_in[16];
    float* out = (float*)d_out;

    initk<<<10, 256>>>();
    phase1<<<dim3(16, 64), 256>>>(inp, pc_emb, addr_emb, enc_W, enc_b,
                                  W_ih, b_ih, b_hh);
    phase2<<<64, 32>>>(h0, c0, W_hh);
    phase3a<<<128, 256>>>(dec_W, dec_b, out);
    phase3b<<<64, 128>>>(addr_emb, enc_W, enc_b, d1_W, d1_b, d2_W, d2_b, out);
}